// round 14
// baseline (speedup 1.0000x reference)
#include <cuda_runtime.h>
#include <cuda_fp16.h>
#include <cstdint>

// Problem constants (fixed by the dataset)
#define NNODES 50000
#define NEDGES 800000
#define D      64
#define H      4
#define HD     256                 // H*D
#define CAP    64                  // slots per node (Poisson(16) edges; self-loop handled analytically)

// -------- scratch (static device globals; no allocation allowed) --------
__device__ __align__(16) __half g_z[NNODES * HD];     // normalized per-head aggregates (25.6 MB)
__device__ __align__(16) __half g_B[D * HD];          // GEMM2 B: B[d][t]=W[(t&~63)+d][t&63] (32 KB)
__device__ __align__(16) float  g_v[2 * H * D];       // logit vectors [src/dst][h][k]
__device__ __align__(16) float  g_asrc[NNODES * H];   // per-node src logits
__device__ __align__(16) float  g_adst[NNODES * H];   // per-node dst logits
__device__            int       g_slot[NNODES * CAP]; // bucketed src indices (12.8 MB)
__device__            int       g_cnt[NNODES];        // bucket fill counts

// ---------------- helpers ----------------
__device__ __forceinline__ float lrelu(float a) {
    return a > 0.f ? a : 0.2f * a;
}

// pack (w, w) into a 64-bit f32x2 operand
__device__ __forceinline__ unsigned long long packww(float w) {
    unsigned long long r;
    asm("mov.b64 %0, {%1, %1};" : "=l"(r) : "f"(w));
    return r;
}

// acc += a * b  (packed 2x fp32)
__device__ __forceinline__ void fma2(unsigned long long& acc, unsigned long long a,
                                     unsigned long long b) {
    asm("fma.rn.f32x2 %0, %1, %2, %0;" : "+l"(acc) : "l"(a), "l"(b));
}

// acc = a * b  (packed 2x fp32)
__device__ __forceinline__ unsigned long long mul2(unsigned long long a, unsigned long long b) {
    unsigned long long r;
    asm("mul.rn.f32x2 %0, %1, %2;" : "=l"(r) : "l"(a), "l"(b));
    return r;
}

__device__ __forceinline__ float2 unpack2(unsigned long long a) {
    float lo, hi;
    asm("mov.b64 {%0, %1}, %2;" : "=f"(lo), "=f"(hi) : "l"(a));
    return make_float2(lo, hi);
}

// ---------------- K1: prep — cnt=0, build B, build v ----------------
__global__ void prep_kernel(const float* __restrict__ W,
                            const float* __restrict__ att_src, const float* __restrict__ att_dst) {
    const int i = blockIdx.x * blockDim.x + threadIdx.x;
    if (i < NNODES) g_cnt[i] = 0;
    if (i < HD * D) {   // B[d*256+t] = W[(t&~63)+d][t&63]
        const int d = i >> 8;
        const int t = i & 255;
        g_B[i] = __float2half_rn(W[((t & ~63) + d) * D + (t & 63)]);
    }
    if (i < 2 * H * D) {  // v[which][h][k] = sum_dd att[h*64+dd] * W[(h*64+dd)*64+k]
        const int h = (i >> 6) & 3;
        const int k = i & 63;
        const float* att = (i >= H * D) ? att_dst : att_src;
        float s = 0.f;
        #pragma unroll
        for (int dd = 0; dd < D; dd++)
            s += att[h * D + dd] * W[(h * D + dd) * D + k];
        g_v[i] = s;
    }
}

// ---------------- K2: bucket scatter (2 edges/thread, no scan needed) ----------------
__global__ void edge_scatter_kernel(const int* __restrict__ ei) {
    const int e = 2 * (blockIdx.x * blockDim.x + threadIdx.x);
    if (e >= NEDGES) return;
    const int2 sp = *(const int2*)(ei + e);
    const int2 dp = *(const int2*)(ei + NEDGES + e);
    int p0 = atomicAdd(&g_cnt[dp.x], 1);
    g_slot[dp.x * CAP + p0] = sp.x;
    int p1 = atomicAdd(&g_cnt[dp.y], 1);
    g_slot[dp.y * CAP + p1] = sp.y;
}

// ---------------- K3: per-node attention logits via v-vectors (thread per node) ----------------
__global__ void __launch_bounds__(256) logits_kernel(const float* __restrict__ x) {
    __shared__ float sv[8][64];    // [which*4+h][k]
    const int tid = threadIdx.x;
    sv[tid >> 6][tid & 63] = g_v[tid];
    sv[(tid + 256) >> 6][(tid + 256) & 63] = g_v[tid + 256];
    __syncthreads();

    const int n = blockIdx.x * 256 + tid;
    if (n >= NNODES) return;

    float acc[8];
    #pragma unroll
    for (int j = 0; j < 8; j++) acc[j] = 0.f;

    const float4* xp = (const float4*)(x + n * D);
    #pragma unroll
    for (int k4 = 0; k4 < 16; k4++) {
        const float4 xx = xp[k4];
        #pragma unroll
        for (int j = 0; j < 8; j++) {
            acc[j] += xx.x * sv[j][k4 * 4]     + xx.y * sv[j][k4 * 4 + 1]
                    + xx.z * sv[j][k4 * 4 + 2] + xx.w * sv[j][k4 * 4 + 3];
        }
    }
    *(float4*)(g_asrc + n * H) = make_float4(acc[0], acc[1], acc[2], acc[3]);
    *(float4*)(g_adst + n * H) = make_float4(acc[4], acc[5], acc[6], acc[7]);
}

// ---------------- K4 (PROFILED SLOT): fused softmax + raw fp32-x aggregation ----------------
// Warp per node. Lane = (head h = lane>>3, x-dim chunk q = lane&7: dims 8q..8q+7).
// Reads raw fp32 x directly (no conversions) and accumulates with packed f32x2 FMAs
// (4 FFMA2 per edge per lane instead of 8 cvt + 8 FFMA). Self-loop folded analytically.
// Exact per-head denominator; z stored normalized (incl 1/H) in fp16.
__global__ void __launch_bounds__(256) node_agg_kernel(const float* __restrict__ x) {
    const int lane = threadIdx.x & 31;
    const int wid  = threadIdx.x >> 5;
    const int n    = blockIdx.x * 8 + wid;
    if (n >= NNODES) return;

    const int h = lane >> 3;    // head 0..3
    const int q = lane & 7;     // x-dim chunk: dims 8q..8q+7

    const int deg  = g_cnt[n];
    const int base = n * CAP;

    const float ad = g_adst[n * H + h];
    const float* xq = x + q * 8;   // lane-constant column offset

    // self-loop contribution (src = n): initializes accumulators via packed MUL
    float wsum;
    unsigned long long m0, m1, m2, m3;
    {
        const float ws = __expf(lrelu(g_asrc[n * H + h] + ad));
        wsum = ws;
        const ulonglong2 p0 = *(const ulonglong2*)(xq + n * D);
        const ulonglong2 p1 = *(const ulonglong2*)(xq + n * D + 4);
        const unsigned long long ww = packww(ws);
        m0 = mul2(p0.x, ww);
        m1 = mul2(p0.y, ww);
        m2 = mul2(p1.x, ww);
        m3 = mul2(p1.y, ww);
    }

    for (int i = 0; i < deg; i += 2) {
        const int  s0   = g_slot[base + i];
        const bool has1 = (i + 1 < deg);
        const int  s1   = has1 ? g_slot[base + i + 1] : 0;
        const float a0 = g_asrc[s0 * H + h];
        const float a1 = has1 ? g_asrc[s1 * H + h] : 0.f;

        // 32B of raw fp32 x per lane, issued as 4 independent LDG.128
        const ulonglong2 v00 = *(const ulonglong2*)(xq + s0 * D);
        const ulonglong2 v01 = *(const ulonglong2*)(xq + s0 * D + 4);
        const ulonglong2 v10 = *(const ulonglong2*)(xq + s1 * D);
        const ulonglong2 v11 = *(const ulonglong2*)(xq + s1 * D + 4);

        const float w0 = __expf(lrelu(a0 + ad));
        const float w1 = has1 ? __expf(lrelu(a1 + ad)) : 0.f;
        wsum += w0 + w1;

        const unsigned long long ww0 = packww(w0);
        const unsigned long long ww1 = packww(w1);

        fma2(m0, v00.x, ww0);
        fma2(m1, v00.y, ww0);
        fma2(m2, v01.x, ww0);
        fma2(m3, v01.y, ww0);
        fma2(m0, v10.x, ww1);
        fma2(m1, v10.y, ww1);
        fma2(m2, v11.x, ww1);
        fma2(m3, v11.y, ww1);
    }

    // normalize by this head's exact denominator, fold head-mean (1/H); store fp16 z
    const float rd = 0.25f / (wsum + 1e-16f);
    const float2 f0 = unpack2(m0);
    const float2 f1 = unpack2(m1);
    const float2 f2 = unpack2(m2);
    const float2 f3 = unpack2(m3);
    uint4 o;
    __half2 p;
    p = __floats2half2_rn(f0.x * rd, f0.y * rd); o.x = *(unsigned*)&p;
    p = __floats2half2_rn(f1.x * rd, f1.y * rd); o.y = *(unsigned*)&p;
    p = __floats2half2_rn(f2.x * rd, f2.y * rd); o.z = *(unsigned*)&p;
    p = __floats2half2_rn(f3.x * rd, f3.y * rd); o.w = *(unsigned*)&p;
    *(uint4*)(g_z + n * HD + h * D + q * 8) = o;   // coalesced 512B per node
}

// ---------------- K5: GEMM2  out = z @ B + bias  ([50k,256] x [256,64], fp16 mma) ----------------
__global__ void __launch_bounds__(256) gemm2_kernel(const float* __restrict__ bias,
                                                    float* __restrict__ out) {
    const int lane = threadIdx.x & 31;
    const int wid  = threadIdx.x >> 5;
    const int g    = lane >> 2;          // group 0..7
    const int tg   = lane & 3;           // thread-in-group 0..3

    const int r0 = blockIdx.x * 128 + wid * 16 + g;
    const int r1 = r0 + 8;
    const bool v0 = (r0 < NNODES);
    const bool v1 = (r1 < NNODES);

    float acc[8][4];
    #pragma unroll
    for (int nt = 0; nt < 8; nt++)
        #pragma unroll
        for (int j = 0; j < 4; j++) acc[nt][j] = 0.f;

    #pragma unroll
    for (int ks = 0; ks < 16; ks++) {
        const int kk = ks * 16;
        const unsigned a0 = v0 ? *(const unsigned*)(g_z + r0 * HD + kk + tg * 2)     : 0u;
        const unsigned a1 = v1 ? *(const unsigned*)(g_z + r1 * HD + kk + tg * 2)     : 0u;
        const unsigned a2 = v0 ? *(const unsigned*)(g_z + r0 * HD + kk + 8 + tg * 2) : 0u;
        const unsigned a3 = v1 ? *(const unsigned*)(g_z + r1 * HD + kk + 8 + tg * 2) : 0u;

        #pragma unroll
        for (int nt = 0; nt < 8; nt++) {
            const int nn = nt * 8 + g;
            const unsigned b0 = *(const unsigned*)(g_B + nn * HD + kk + tg * 2);
            const unsigned b1 = *(const unsigned*)(g_B + nn * HD + kk + 8 + tg * 2);
            asm volatile(
                "mma.sync.aligned.m16n8k16.row.col.f32.f16.f16.f32 "
                "{%0,%1,%2,%3}, {%4,%5,%6,%7}, {%8,%9}, {%0,%1,%2,%3};"
                : "+f"(acc[nt][0]), "+f"(acc[nt][1]), "+f"(acc[nt][2]), "+f"(acc[nt][3])
                : "r"(a0), "r"(a1), "r"(a2), "r"(a3), "r"(b0), "r"(b1));
        }
    }

    #pragma unroll
    for (int nt = 0; nt < 8; nt++) {
        const int c = nt * 8 + tg * 2;
        const float2 bb = *(const float2*)(bias + c);
        if (v0) *(float2*)(out + r0 * D + c) = make_float2(acc[nt][0] + bb.x, acc[nt][1] + bb.y);
        if (v1) *(float2*)(out + r1 * D + c) = make_float2(acc[nt][2] + bb.x, acc[nt][3] + bb.y);
    }
}

// ---------------- launch ----------------
extern "C" void kernel_launch(void* const* d_in, const int* in_sizes, int n_in,
                              void* d_out, int out_size) {
    const float* x       = (const float*)d_in[0];
    const int*   ei      = (const int*)  d_in[1];
    const float* W       = (const float*)d_in[2];
    const float* att_src = (const float*)d_in[3];
    const float* att_dst = (const float*)d_in[4];
    const float* bias    = (const float*)d_in[5];
    float* out = (float*)d_out;

    // 1: prep (cnt=0, B, v)
    prep_kernel<<<(NNODES + 255) / 256, 256>>>(W, att_src, att_dst);

    // 2: bucket scatter (real edges only; self-loops folded into agg)
    edge_scatter_kernel<<<(NEDGES / 2 + 255) / 256, 256>>>(ei);

    // 3: attention logits
    logits_kernel<<<(NNODES + 255) / 256, 256>>>(x);

    // 4: fused softmax + aggregation  <-- profiled slot
    node_agg_kernel<<<(NNODES + 7) / 8, 256>>>(x);

    // 5: out = z @ B + bias (tensor cores)
    gemm2_kernel<<<(NNODES + 127) / 128, 256>>>(bias, out);
}

// round 15
// speedup vs baseline: 1.1533x; 1.1533x over previous
#include <cuda_runtime.h>
#include <cuda_fp16.h>
#include <cstdint>

// Problem constants (fixed by the dataset)
#define NNODES 50000
#define NEDGES 800000
#define D      64
#define H      4
#define HD     256                 // H*D
#define CAP    64                  // slots per node (Poisson(16) edges; self-loop handled analytically)

#define SCAT_NB ((NEDGES / 2 + 255) / 256)     // 1563 scatter blocks (2 edges/thread)
#define LOGIT_NB ((NNODES + 255) / 256)        // 196 logits blocks

// -------- scratch (static device globals; no allocation allowed) --------
__device__ __align__(16) __half g_xf[NNODES * D];     // x in fp16 [N,64]               (6.4 MB)
__device__ __align__(16) __half g_z[NNODES * HD];     // normalized per-head aggregates (25.6 MB)
__device__ __align__(16) __half g_B[D * HD];          // GEMM2 B: B[d][t]=W[(t&~63)+d][t&63] (32 KB)
__device__ __align__(16) float  g_v[2 * H * D];       // logit vectors [src/dst][h][k]
__device__ __align__(16) float  g_asrc[NNODES * H];   // per-node src logits
__device__ __align__(16) float  g_adst[NNODES * H];   // per-node dst logits
__device__ __align__(16) int    g_slot[NNODES * CAP]; // bucketed src indices (12.8 MB)
__device__            int       g_cnt[NNODES];        // bucket fill counts

// ---------------- helpers ----------------
__device__ __forceinline__ float lrelu(float a) {
    return a > 0.f ? a : 0.2f * a;
}

// ---------------- K1: prep — x->fp16, cnt=0, build B, build v ----------------
__global__ void prep_kernel(const float* __restrict__ x, const float* __restrict__ W,
                            const float* __restrict__ att_src, const float* __restrict__ att_dst) {
    const int i = blockIdx.x * blockDim.x + threadIdx.x;
    if (i < NNODES * D / 2) {
        const float2 f = *(const float2*)(x + 2 * i);
        *(__half2*)(g_xf + 2 * i) = __floats2half2_rn(f.x, f.y);
    }
    if (i < NNODES) g_cnt[i] = 0;
    if (i < HD * D) {   // B[d*256+t] = W[(t&~63)+d][t&63]
        const int d = i >> 8;
        const int t = i & 255;
        g_B[i] = __float2half_rn(W[((t & ~63) + d) * D + (t & 63)]);
    }
    if (i < 2 * H * D) {  // v[which][h][k] = sum_dd att[h*64+dd] * W[(h*64+dd)*64+k]
        const int h = (i >> 6) & 3;
        const int k = i & 63;
        const float* att = (i >= H * D) ? att_dst : att_src;
        float s = 0.f;
        #pragma unroll
        for (int dd = 0; dd < D; dd++)
            s += att[h * D + dd] * W[(h * D + dd) * D + k];
        g_v[i] = s;
    }
}

// ---------------- K2: fused bucket scatter + logits (disjoint block ranges) ----------------
__global__ void __launch_bounds__(256) scatter_logits_kernel(const int* __restrict__ ei,
                                                             const float* __restrict__ x) {
    if (blockIdx.x < SCAT_NB) {
        // ----- scatter: 2 edges/thread -----
        const int e = 2 * (blockIdx.x * 256 + threadIdx.x);
        if (e >= NEDGES) return;
        const int2 sp = *(const int2*)(ei + e);
        const int2 dp = *(const int2*)(ei + NEDGES + e);
        int p0 = atomicAdd(&g_cnt[dp.x], 1);
        g_slot[dp.x * CAP + p0] = sp.x;
        int p1 = atomicAdd(&g_cnt[dp.y], 1);
        g_slot[dp.y * CAP + p1] = sp.y;
        return;
    }

    // ----- logits: thread per node -----
    __shared__ float sv[8][64];    // [which*4+h][k]
    const int tid = threadIdx.x;
    sv[tid >> 6][tid & 63] = g_v[tid];
    sv[(tid + 256) >> 6][(tid + 256) & 63] = g_v[tid + 256];
    __syncthreads();

    const int n = (blockIdx.x - SCAT_NB) * 256 + tid;
    if (n >= NNODES) return;

    float acc[8];
    #pragma unroll
    for (int j = 0; j < 8; j++) acc[j] = 0.f;

    const float4* xp = (const float4*)(x + n * D);
    #pragma unroll
    for (int k4 = 0; k4 < 16; k4++) {
        const float4 xx = xp[k4];
        #pragma unroll
        for (int j = 0; j < 8; j++) {
            acc[j] += xx.x * sv[j][k4 * 4]     + xx.y * sv[j][k4 * 4 + 1]
                    + xx.z * sv[j][k4 * 4 + 2] + xx.w * sv[j][k4 * 4 + 3];
        }
    }
    *(float4*)(g_asrc + n * H) = make_float4(acc[0], acc[1], acc[2], acc[3]);
    *(float4*)(g_adst + n * H) = make_float4(acc[4], acc[5], acc[6], acc[7]);
}

// ---------------- K3: fused softmax + aggregation (warp per node, HFMA2 groups) ----------------
// Lane = (head h = lane>>3, x-dim chunk q = lane&7: dims 8q..8q+7). 4 edges per iteration:
// slots fetched with one int4 load, per-edge fp16 weights applied with HMUL2/HFMA2 into
// fp16 group accumulators, flushed to fp32 every 4 edges (bounds fp16 rounding error).
// Invalid tail slots use src=n with w=0 (safe, NaN-free). Exact per-head denominator.
__global__ void __launch_bounds__(256) node_agg_kernel() {
    const int lane = threadIdx.x & 31;
    const int wid  = threadIdx.x >> 5;
    const int n    = blockIdx.x * 8 + wid;
    if (n >= NNODES) return;

    const int h = lane >> 3;    // head 0..3
    const int q = lane & 7;     // x-dim chunk: dims 8q..8q+7

    const int deg  = g_cnt[n];
    const int base = n * CAP;

    const float ad = g_adst[n * H + h];

    // self-loop contribution (src = n) in fp32
    float wsum;
    float m[8];
    {
        const float ws = __expf(lrelu(g_asrc[n * H + h] + ad));
        wsum = ws;
        const uint4 v = *(const uint4*)(g_xf + n * D + q * 8);
        const float2 f0 = __half22float2(*(const __half2*)&v.x);
        const float2 f1 = __half22float2(*(const __half2*)&v.y);
        const float2 f2 = __half22float2(*(const __half2*)&v.z);
        const float2 f3 = __half22float2(*(const __half2*)&v.w);
        m[0] = ws * f0.x; m[1] = ws * f0.y;
        m[2] = ws * f1.x; m[3] = ws * f1.y;
        m[4] = ws * f2.x; m[5] = ws * f2.y;
        m[6] = ws * f3.x; m[7] = ws * f3.y;
    }

    for (int i = 0; i < deg; i += 4) {
        const int4 ss = *(const int4*)(g_slot + base + i);   // 4 slots, one 16B broadcast load
        const bool h1 = (i + 1 < deg);
        const bool h2 = (i + 2 < deg);
        const bool h3 = (i + 3 < deg);
        const int s0 = ss.x;
        const int s1 = h1 ? ss.y : n;
        const int s2 = h2 ? ss.z : n;
        const int s3 = h3 ? ss.w : n;

        const float a0 = g_asrc[s0 * H + h];
        const float a1 = g_asrc[s1 * H + h];
        const float a2 = g_asrc[s2 * H + h];
        const float a3 = g_asrc[s3 * H + h];

        const uint4 v0 = *(const uint4*)(g_xf + s0 * D + q * 8);
        const uint4 v1 = *(const uint4*)(g_xf + s1 * D + q * 8);
        const uint4 v2 = *(const uint4*)(g_xf + s2 * D + q * 8);
        const uint4 v3 = *(const uint4*)(g_xf + s3 * D + q * 8);

        const float w0 = __expf(lrelu(a0 + ad));
        const float w1 = h1 ? __expf(lrelu(a1 + ad)) : 0.f;
        const float w2 = h2 ? __expf(lrelu(a2 + ad)) : 0.f;
        const float w3 = h3 ? __expf(lrelu(a3 + ad)) : 0.f;
        wsum += (w0 + w1) + (w2 + w3);

        const __half2 ww0 = __floats2half2_rn(w0, w0);
        const __half2 ww1 = __floats2half2_rn(w1, w1);
        const __half2 ww2 = __floats2half2_rn(w2, w2);
        const __half2 ww3 = __floats2half2_rn(w3, w3);

        // fp16 group accumulation: 4 data-pairs x (1 HMUL2 + 3 HFMA2)
        __half2 acc0 = __hmul2(ww0, *(const __half2*)&v0.x);
        __half2 acc1 = __hmul2(ww0, *(const __half2*)&v0.y);
        __half2 acc2 = __hmul2(ww0, *(const __half2*)&v0.z);
        __half2 acc3 = __hmul2(ww0, *(const __half2*)&v0.w);
        acc0 = __hfma2(ww1, *(const __half2*)&v1.x, acc0);
        acc1 = __hfma2(ww1, *(const __half2*)&v1.y, acc1);
        acc2 = __hfma2(ww1, *(const __half2*)&v1.z, acc2);
        acc3 = __hfma2(ww1, *(const __half2*)&v1.w, acc3);
        acc0 = __hfma2(ww2, *(const __half2*)&v2.x, acc0);
        acc1 = __hfma2(ww2, *(const __half2*)&v2.y, acc1);
        acc2 = __hfma2(ww2, *(const __half2*)&v2.z, acc2);
        acc3 = __hfma2(ww2, *(const __half2*)&v2.w, acc3);
        acc0 = __hfma2(ww3, *(const __half2*)&v3.x, acc0);
        acc1 = __hfma2(ww3, *(const __half2*)&v3.y, acc1);
        acc2 = __hfma2(ww3, *(const __half2*)&v3.z, acc2);
        acc3 = __hfma2(ww3, *(const __half2*)&v3.w, acc3);

        // flush group partials to fp32
        const float2 g0 = __half22float2(acc0);
        const float2 g1 = __half22float2(acc1);
        const float2 g2 = __half22float2(acc2);
        const float2 g3 = __half22float2(acc3);
        m[0] += g0.x; m[1] += g0.y;
        m[2] += g1.x; m[3] += g1.y;
        m[4] += g2.x; m[5] += g2.y;
        m[6] += g3.x; m[7] += g3.y;
    }

    // normalize by this head's exact denominator, fold head-mean (1/H); store fp16 z
    const float rd = 0.25f / (wsum + 1e-16f);
    uint4 o;
    __half2 p;
    p = __floats2half2_rn(m[0] * rd, m[1] * rd); o.x = *(unsigned*)&p;
    p = __floats2half2_rn(m[2] * rd, m[3] * rd); o.y = *(unsigned*)&p;
    p = __floats2half2_rn(m[4] * rd, m[5] * rd); o.z = *(unsigned*)&p;
    p = __floats2half2_rn(m[6] * rd, m[7] * rd); o.w = *(unsigned*)&p;
    *(uint4*)(g_z + n * HD + h * D + q * 8) = o;   // coalesced 512B per node
}

// ---------------- K4 (PROFILED SLOT): GEMM2  out = z @ B + bias ----------------
__global__ void __launch_bounds__(256) gemm2_kernel(const float* __restrict__ bias,
                                                    float* __restrict__ out) {
    const int lane = threadIdx.x & 31;
    const int wid  = threadIdx.x >> 5;
    const int g    = lane >> 2;          // group 0..7
    const int tg   = lane & 3;           // thread-in-group 0..3

    const int r0 = blockIdx.x * 128 + wid * 16 + g;
    const int r1 = r0 + 8;
    const bool v0 = (r0 < NNODES);
    const bool v1 = (r1 < NNODES);

    float acc[8][4];
    #pragma unroll
    for (int nt = 0; nt < 8; nt++)
        #pragma unroll
        for (int j = 0; j < 4; j++) acc[nt][j] = 0.f;

    #pragma unroll
    for (int ks = 0; ks < 16; ks++) {
        const int kk = ks * 16;
        const unsigned a0 = v0 ? *(const unsigned*)(g_z + r0 * HD + kk + tg * 2)     : 0u;
        const unsigned a1 = v1 ? *(const unsigned*)(g_z + r1 * HD + kk + tg * 2)     : 0u;
        const unsigned a2 = v0 ? *(const unsigned*)(g_z + r0 * HD + kk + 8 + tg * 2) : 0u;
        const unsigned a3 = v1 ? *(const unsigned*)(g_z + r1 * HD + kk + 8 + tg * 2) : 0u;

        #pragma unroll
        for (int nt = 0; nt < 8; nt++) {
            const int nn = nt * 8 + g;
            const unsigned b0 = *(const unsigned*)(g_B + nn * HD + kk + tg * 2);
            const unsigned b1 = *(const unsigned*)(g_B + nn * HD + kk + 8 + tg * 2);
            asm volatile(
                "mma.sync.aligned.m16n8k16.row.col.f32.f16.f16.f32 "
                "{%0,%1,%2,%3}, {%4,%5,%6,%7}, {%8,%9}, {%0,%1,%2,%3};"
                : "+f"(acc[nt][0]), "+f"(acc[nt][1]), "+f"(acc[nt][2]), "+f"(acc[nt][3])
                : "r"(a0), "r"(a1), "r"(a2), "r"(a3), "r"(b0), "r"(b1));
        }
    }

    #pragma unroll
    for (int nt = 0; nt < 8; nt++) {
        const int c = nt * 8 + tg * 2;
        const float2 bb = *(const float2*)(bias + c);
        if (v0) *(float2*)(out + r0 * D + c) = make_float2(acc[nt][0] + bb.x, acc[nt][1] + bb.y);
        if (v1) *(float2*)(out + r1 * D + c) = make_float2(acc[nt][2] + bb.x, acc[nt][3] + bb.y);
    }
}

// ---------------- launch ----------------
extern "C" void kernel_launch(void* const* d_in, const int* in_sizes, int n_in,
                              void* d_out, int out_size) {
    const float* x       = (const float*)d_in[0];
    const int*   ei      = (const int*)  d_in[1];
    const float* W       = (const float*)d_in[2];
    const float* att_src = (const float*)d_in[3];
    const float* att_dst = (const float*)d_in[4];
    const float* bias    = (const float*)d_in[5];
    float* out = (float*)d_out;

    // 1: prep (x->fp16, cnt=0, B, v)
    prep_kernel<<<(NNODES * D / 2 + 255) / 256, 256>>>(x, W, att_src, att_dst);

    // 2: fused bucket scatter + logits
    scatter_logits_kernel<<<SCAT_NB + LOGIT_NB, 256>>>(ei, x);

    // 3: fused softmax + aggregation (HFMA2 groups)
    node_agg_kernel<<<(NNODES + 7) / 8, 256>>>();

    // 4: out = z @ B + bias  <-- profiled slot
    gemm2_kernel<<<(NNODES + 127) / 128, 256>>>(bias, out);
}

// round 16
// speedup vs baseline: 1.2975x; 1.1250x over previous
#include <cuda_runtime.h>
#include <cuda_fp16.h>
#include <cstdint>

// Problem constants (fixed by the dataset)
#define NNODES 50000
#define NEDGES 800000
#define D      64
#define H      4
#define HD     256                 // H*D
#define CAP    64                  // slots per node (Poisson(16) edges; self-loop handled analytically)

#define SCAT_NB ((NEDGES / 2 + 255) / 256)     // scatter blocks (2 edges/thread)
#define LOGIT_NB ((NNODES + 255) / 256)        // logits blocks

#define SST 264                                 // smem row stride in halves (bank-conflict-free)
#define GEMM2_SMEM ((128 + 64) * SST * 2)       // 101376 bytes

// -------- scratch (static device globals; no allocation allowed) --------
__device__ __align__(16) __half g_xf[NNODES * D];     // x in fp16 [N,64]               (6.4 MB)
__device__ __align__(16) __half g_z[NNODES * HD];     // normalized per-head aggregates (25.6 MB)
__device__ __align__(16) __half g_B[D * HD];          // GEMM2 B: B[d][t]=W[(t&~63)+d][t&63] (32 KB)
__device__ __align__(16) float  g_v[2 * H * D];       // logit vectors [src/dst][h][k]
__device__ __align__(16) float  g_asrc[NNODES * H];   // per-node src logits
__device__ __align__(16) float  g_adst[NNODES * H];   // per-node dst logits
__device__ __align__(16) int    g_slot[NNODES * CAP]; // bucketed src indices (12.8 MB)
__device__            int       g_cnt[NNODES];        // bucket fill counts

// ---------------- helpers ----------------
__device__ __forceinline__ float lrelu(float a) {
    return a > 0.f ? a : 0.2f * a;
}

__device__ __forceinline__ unsigned smem_u32(const void* p) {
    return (unsigned)__cvta_generic_to_shared(p);
}

// ---------------- K1: prep — x->fp16, cnt=0, build B, build v ----------------
__global__ void prep_kernel(const float* __restrict__ x, const float* __restrict__ W,
                            const float* __restrict__ att_src, const float* __restrict__ att_dst) {
    const int i = blockIdx.x * blockDim.x + threadIdx.x;
    if (i < NNODES * D / 2) {
        const float2 f = *(const float2*)(x + 2 * i);
        *(__half2*)(g_xf + 2 * i) = __floats2half2_rn(f.x, f.y);
    }
    if (i < NNODES) g_cnt[i] = 0;
    if (i < HD * D) {   // B[d*256+t] = W[(t&~63)+d][t&63]  -> stored as g_B[n][k], n=0..63, k=0..255
        const int d = i >> 8;
        const int t = i & 255;
        g_B[i] = __float2half_rn(W[((t & ~63) + d) * D + (t & 63)]);
    }
    if (i < 2 * H * D) {  // v[which][h][k] = sum_dd att[h*64+dd] * W[(h*64+dd)*64+k]
        const int h = (i >> 6) & 3;
        const int k = i & 63;
        const float* att = (i >= H * D) ? att_dst : att_src;
        float s = 0.f;
        #pragma unroll
        for (int dd = 0; dd < D; dd++)
            s += att[h * D + dd] * W[(h * D + dd) * D + k];
        g_v[i] = s;
    }
}

// ---------------- K2: fused bucket scatter + logits (disjoint block ranges) ----------------
__global__ void __launch_bounds__(256) scatter_logits_kernel(const int* __restrict__ ei,
                                                             const float* __restrict__ x) {
    if (blockIdx.x < SCAT_NB) {
        const int e = 2 * (blockIdx.x * 256 + threadIdx.x);
        if (e >= NEDGES) return;
        const int2 sp = *(const int2*)(ei + e);
        const int2 dp = *(const int2*)(ei + NEDGES + e);
        int p0 = atomicAdd(&g_cnt[dp.x], 1);
        g_slot[dp.x * CAP + p0] = sp.x;
        int p1 = atomicAdd(&g_cnt[dp.y], 1);
        g_slot[dp.y * CAP + p1] = sp.y;
        return;
    }

    __shared__ float sv[8][64];    // [which*4+h][k]
    const int tid = threadIdx.x;
    sv[tid >> 6][tid & 63] = g_v[tid];
    sv[(tid + 256) >> 6][(tid + 256) & 63] = g_v[tid + 256];
    __syncthreads();

    const int n = (blockIdx.x - SCAT_NB) * 256 + tid;
    if (n >= NNODES) return;

    float acc[8];
    #pragma unroll
    for (int j = 0; j < 8; j++) acc[j] = 0.f;

    const float4* xp = (const float4*)(x + n * D);
    #pragma unroll
    for (int k4 = 0; k4 < 16; k4++) {
        const float4 xx = xp[k4];
        #pragma unroll
        for (int j = 0; j < 8; j++) {
            acc[j] += xx.x * sv[j][k4 * 4]     + xx.y * sv[j][k4 * 4 + 1]
                    + xx.z * sv[j][k4 * 4 + 2] + xx.w * sv[j][k4 * 4 + 3];
        }
    }
    *(float4*)(g_asrc + n * H) = make_float4(acc[0], acc[1], acc[2], acc[3]);
    *(float4*)(g_adst + n * H) = make_float4(acc[4], acc[5], acc[6], acc[7]);
}

// ---------------- K3: fused softmax + aggregation (warp per node, HFMA2 groups) ----------------
__global__ void __launch_bounds__(256) node_agg_kernel() {
    const int lane = threadIdx.x & 31;
    const int wid  = threadIdx.x >> 5;
    const int n    = blockIdx.x * 8 + wid;
    if (n >= NNODES) return;

    const int h = lane >> 3;    // head 0..3
    const int q = lane & 7;     // x-dim chunk: dims 8q..8q+7

    const int deg  = g_cnt[n];
    const int base = n * CAP;

    const float ad = g_adst[n * H + h];

    // self-loop contribution (src = n) in fp32
    float wsum;
    float m[8];
    {
        const float ws = __expf(lrelu(g_asrc[n * H + h] + ad));
        wsum = ws;
        const uint4 v = *(const uint4*)(g_xf + n * D + q * 8);
        const float2 f0 = __half22float2(*(const __half2*)&v.x);
        const float2 f1 = __half22float2(*(const __half2*)&v.y);
        const float2 f2 = __half22float2(*(const __half2*)&v.z);
        const float2 f3 = __half22float2(*(const __half2*)&v.w);
        m[0] = ws * f0.x; m[1] = ws * f0.y;
        m[2] = ws * f1.x; m[3] = ws * f1.y;
        m[4] = ws * f2.x; m[5] = ws * f2.y;
        m[6] = ws * f3.x; m[7] = ws * f3.y;
    }

    for (int i = 0; i < deg; i += 4) {
        const int4 ss = *(const int4*)(g_slot + base + i);
        const bool h1 = (i + 1 < deg);
        const bool h2 = (i + 2 < deg);
        const bool h3 = (i + 3 < deg);
        const int s0 = ss.x;
        const int s1 = h1 ? ss.y : n;
        const int s2 = h2 ? ss.z : n;
        const int s3 = h3 ? ss.w : n;

        const float a0 = g_asrc[s0 * H + h];
        const float a1 = g_asrc[s1 * H + h];
        const float a2 = g_asrc[s2 * H + h];
        const float a3 = g_asrc[s3 * H + h];

        const uint4 v0 = *(const uint4*)(g_xf + s0 * D + q * 8);
        const uint4 v1 = *(const uint4*)(g_xf + s1 * D + q * 8);
        const uint4 v2 = *(const uint4*)(g_xf + s2 * D + q * 8);
        const uint4 v3 = *(const uint4*)(g_xf + s3 * D + q * 8);

        const float w0 = __expf(lrelu(a0 + ad));
        const float w1 = h1 ? __expf(lrelu(a1 + ad)) : 0.f;
        const float w2 = h2 ? __expf(lrelu(a2 + ad)) : 0.f;
        const float w3 = h3 ? __expf(lrelu(a3 + ad)) : 0.f;
        wsum += (w0 + w1) + (w2 + w3);

        const __half2 ww0 = __floats2half2_rn(w0, w0);
        const __half2 ww1 = __floats2half2_rn(w1, w1);
        const __half2 ww2 = __floats2half2_rn(w2, w2);
        const __half2 ww3 = __floats2half2_rn(w3, w3);

        __half2 acc0 = __hmul2(ww0, *(const __half2*)&v0.x);
        __half2 acc1 = __hmul2(ww0, *(const __half2*)&v0.y);
        __half2 acc2 = __hmul2(ww0, *(const __half2*)&v0.z);
        __half2 acc3 = __hmul2(ww0, *(const __half2*)&v0.w);
        acc0 = __hfma2(ww1, *(const __half2*)&v1.x, acc0);
        acc1 = __hfma2(ww1, *(const __half2*)&v1.y, acc1);
        acc2 = __hfma2(ww1, *(const __half2*)&v1.z, acc2);
        acc3 = __hfma2(ww1, *(const __half2*)&v1.w, acc3);
        acc0 = __hfma2(ww2, *(const __half2*)&v2.x, acc0);
        acc1 = __hfma2(ww2, *(const __half2*)&v2.y, acc1);
        acc2 = __hfma2(ww2, *(const __half2*)&v2.z, acc2);
        acc3 = __hfma2(ww2, *(const __half2*)&v2.w, acc3);
        acc0 = __hfma2(ww3, *(const __half2*)&v3.x, acc0);
        acc1 = __hfma2(ww3, *(const __half2*)&v3.y, acc1);
        acc2 = __hfma2(ww3, *(const __half2*)&v3.z, acc2);
        acc3 = __hfma2(ww3, *(const __half2*)&v3.w, acc3);

        const float2 g0 = __half22float2(acc0);
        const float2 g1 = __half22float2(acc1);
        const float2 g2 = __half22float2(acc2);
        const float2 g3 = __half22float2(acc3);
        m[0] += g0.x; m[1] += g0.y;
        m[2] += g1.x; m[3] += g1.y;
        m[4] += g2.x; m[5] += g2.y;
        m[6] += g3.x; m[7] += g3.y;
    }

    const float rd = 0.25f / (wsum + 1e-16f);
    uint4 o;
    __half2 p;
    p = __floats2half2_rn(m[0] * rd, m[1] * rd); o.x = *(unsigned*)&p;
    p = __floats2half2_rn(m[2] * rd, m[3] * rd); o.y = *(unsigned*)&p;
    p = __floats2half2_rn(m[4] * rd, m[5] * rd); o.z = *(unsigned*)&p;
    p = __floats2half2_rn(m[6] * rd, m[7] * rd); o.w = *(unsigned*)&p;
    *(uint4*)(g_z + n * HD + h * D + q * 8) = o;
}

// ---------------- K4 (PROFILED SLOT): smem-staged GEMM2  out = z @ B + bias ----------------
// Block = 128 rows of z. z-tile (128x256) and B (64x256) staged in dynamic smem with
// row stride 264 halves (528B -> 4-word offset per row: ldmatrix conflict-free).
// All fragments loaded via ldmatrix.m8n8.x4 from smem.
__global__ void __launch_bounds__(256) gemm2_kernel(const float* __restrict__ bias,
                                                    float* __restrict__ out) {
    extern __shared__ __align__(16) __half sm[];
    __half* sZ = sm;                 // [128][SST]
    __half* sB = sm + 128 * SST;     // [64][SST]

    const int tid  = threadIdx.x;
    const int row0 = blockIdx.x * 128;

    // stage B: 64 rows x 32 uint4
    for (int idx = tid; idx < 64 * 32; idx += 256) {
        const int r = idx >> 5, c8 = idx & 31;
        *(uint4*)(sB + r * SST + c8 * 8) = *(const uint4*)(g_B + r * HD + c8 * 8);
    }
    // stage z-tile: 128 rows x 32 uint4 (zero-fill past NNODES)
    for (int idx = tid; idx < 128 * 32; idx += 256) {
        const int r = idx >> 5, c8 = idx & 31;
        uint4 v = make_uint4(0u, 0u, 0u, 0u);
        if (row0 + r < NNODES) v = *(const uint4*)(g_z + (row0 + r) * HD + c8 * 8);
        *(uint4*)(sZ + r * SST + c8 * 8) = v;
    }
    __syncthreads();

    const int lane = tid & 31;
    const int wid  = tid >> 5;
    const int R    = wid * 16;       // warp's 16-row band
    const int g    = lane >> 2;
    const int tg   = lane & 3;

    // A ldmatrix lane address: row R + (lane&15), col kk + (lane>=16 ? 8 : 0)
    const unsigned aBase = smem_u32(sZ + (R + (lane & 15)) * SST + ((lane & 16) ? 8 : 0));
    // B ldmatrix lane address: n = (lane&7) + (lane&16 ? 8 : 0), col kk + (lane&8 ? 8 : 0)
    const unsigned bBase = smem_u32(sB + ((lane & 7) + ((lane & 16) ? 8 : 0)) * SST
                                       + ((lane & 8) ? 8 : 0));

    float acc[8][4];
    #pragma unroll
    for (int nt = 0; nt < 8; nt++)
        #pragma unroll
        for (int j = 0; j < 4; j++) acc[nt][j] = 0.f;

    #pragma unroll
    for (int ks = 0; ks < 16; ks++) {
        const int kk = ks * 16;

        unsigned a0, a1, a2, a3;
        asm volatile("ldmatrix.sync.aligned.m8n8.x4.shared.b16 {%0,%1,%2,%3}, [%4];"
                     : "=r"(a0), "=r"(a1), "=r"(a2), "=r"(a3)
                     : "r"(aBase + kk * 2));

        #pragma unroll
        for (int p = 0; p < 4; p++) {   // nt pair: covers nt=2p, 2p+1 (n0 = p*16)
            unsigned b0, b1, b2, b3;
            asm volatile("ldmatrix.sync.aligned.m8n8.x4.shared.b16 {%0,%1,%2,%3}, [%4];"
                         : "=r"(b0), "=r"(b1), "=r"(b2), "=r"(b3)
                         : "r"(bBase + (p * 16 * SST + kk) * 2));
            asm volatile(
                "mma.sync.aligned.m16n8k16.row.col.f32.f16.f16.f32 "
                "{%0,%1,%2,%3}, {%4,%5,%6,%7}, {%8,%9}, {%0,%1,%2,%3};"
                : "+f"(acc[2*p][0]), "+f"(acc[2*p][1]), "+f"(acc[2*p][2]), "+f"(acc[2*p][3])
                : "r"(a0), "r"(a1), "r"(a2), "r"(a3), "r"(b0), "r"(b1));
            asm volatile(
                "mma.sync.aligned.m16n8k16.row.col.f32.f16.f16.f32 "
                "{%0,%1,%2,%3}, {%4,%5,%6,%7}, {%8,%9}, {%0,%1,%2,%3};"
                : "+f"(acc[2*p+1][0]), "+f"(acc[2*p+1][1]), "+f"(acc[2*p+1][2]), "+f"(acc[2*p+1][3])
                : "r"(a0), "r"(a1), "r"(a2), "r"(a3), "r"(b2), "r"(b3));
        }
    }

    const int r0 = row0 + R + g;
    const int r1 = r0 + 8;
    const bool v0 = (r0 < NNODES);
    const bool v1 = (r1 < NNODES);

    #pragma unroll
    for (int nt = 0; nt < 8; nt++) {
        const int c = nt * 8 + tg * 2;
        const float2 bb = *(const float2*)(bias + c);
        if (v0) *(float2*)(out + r0 * D + c) = make_float2(acc[nt][0] + bb.x, acc[nt][1] + bb.y);
        if (v1) *(float2*)(out + r1 * D + c) = make_float2(acc[nt][2] + bb.x, acc[nt][3] + bb.y);
    }
}

// ---------------- launch ----------------
extern "C" void kernel_launch(void* const* d_in, const int* in_sizes, int n_in,
                              void* d_out, int out_size) {
    const float* x       = (const float*)d_in[0];
    const int*   ei      = (const int*)  d_in[1];
    const float* W       = (const float*)d_in[2];
    const float* att_src = (const float*)d_in[3];
    const float* att_dst = (const float*)d_in[4];
    const float* bias    = (const float*)d_in[5];
    float* out = (float*)d_out;

    // raise dynamic smem cap for gemm2 (idempotent host call; not a stream op)
    cudaFuncSetAttribute(gemm2_kernel, cudaFuncAttributeMaxDynamicSharedMemorySize, GEMM2_SMEM);

    // 1: prep (x->fp16, cnt=0, B, v)
    prep_kernel<<<(NNODES * D / 2 + 255) / 256, 256>>>(x, W, att_src, att_dst);

    // 2: fused bucket scatter + logits
    scatter_logits_kernel<<<SCAT_NB + LOGIT_NB, 256>>>(ei, x);

    // 3: fused softmax + aggregation (HFMA2 groups)
    node_agg_kernel<<<(NNODES + 7) / 8, 256>>>();

    // 4: out = z @ B + bias, smem-staged + ldmatrix  <-- profiled slot
    gemm2_kernel<<<(NNODES + 127) / 128, 256, GEMM2_SMEM>>>(bias, out);
}